// round 11
// baseline (speedup 1.0000x reference)
#include <cuda_runtime.h>
#include <cuda_bf16.h>
#include <cstdint>
#include <math.h>

#define N 8192
#define D 128
#define NCTA 148
#define NTT 2080               /* upper-triangle tiles: 64*65/2 */
#define NTHR 512
#define NBUCK 4096
#define NSUB 512               /* 16-row subchunks */
#define INV_T 14.2857142857142857f
#define LN2 0.69314718055994531f
#define SQRT_C 4.5398160486f   /* sqrt((1/0.07)*log2(e)) */
#define THRESH 0.1f

// Scratch (no cudaMalloc allowed)
__device__ __nv_bfloat16 g_fbf[N * D];       // normalized * SQRT_C, bf16
__device__ float g_fn[N * D];                // normalized, fp32
__device__ float g_fp[N * D];                // normalized, sorted order
__device__ float g_pref[(N + 1) * D];        // exclusive prefix sums (sorted)
__device__ float g_ssum[NSUB * D];           // 16-row subchunk sums
__device__ float g_soff[NSUB * D];           // exclusive subchunk offsets
__device__ float g_slab[N];                  // sorted labels
__device__ int   g_sidx[N];                  // sorted -> original index
__device__ float g_den[N];
__device__ float g_loss;
__device__ unsigned g_cnt_gemm, g_cnt_out;

// ---- main kernel SMEM layout (bytes) ----
#define SM_RES   0          /* resident 128-row j-strip, 32 KB, XOR-swizzled */
#define SM_STR   32768      /* 2 x 32 KB double-buffered streaming A tiles */
#define SM_TOTAL 98304

__device__ __forceinline__ uint32_t smem_u32(const void* p) {
    uint32_t a;
    asm("{ .reg .u64 t; cvta.to.shared.u64 t, %1; cvt.u32.u64 %0, t; }" : "=r"(a) : "l"(p));
    return a;
}
__device__ __forceinline__ float ex2(float x) {
    float r;
    asm("ex2.approx.ftz.f32 %0, %1;" : "=f"(r) : "f"(x));
    return r;
}
__device__ __forceinline__ unsigned ld_acq(unsigned* p) {
    unsigned v;
    asm volatile("ld.acquire.gpu.u32 %0, [%1];" : "=r"(v) : "l"(p) : "memory");
    return v;
}

#define LDSM_X4(r0, r1, r2, r3, addr) \
    asm volatile("ldmatrix.sync.aligned.m8n8.x4.shared.b16 {%0,%1,%2,%3}, [%4];" \
                 : "=r"(r0), "=r"(r1), "=r"(r2), "=r"(r3) : "r"(addr))

#define MMA16816(d, a, b) \
    asm volatile("mma.sync.aligned.m16n8k16.row.col.f32.bf16.bf16.f32 " \
                 "{%0,%1,%2,%3}, {%4,%5,%6,%7}, {%8,%9}, {%0,%1,%2,%3};" \
                 : "+f"((d)[0]), "+f"((d)[1]), "+f"((d)[2]), "+f"((d)[3]) \
                 : "r"((a)[0]), "r"((a)[1]), "r"((a)[2]), "r"((a)[3]), \
                   "r"((b)[0]), "r"((b)[1]))

#define CP_ASYNC16(dst, src) \
    asm volatile("cp.async.cg.shared.global [%0], [%1], 16;" \
                 :: "r"(dst), "l"(src) : "memory")
#define CP_COMMIT() asm volatile("cp.async.commit_group;" ::: "memory")
#define CP_WAIT0()  asm volatile("cp.async.wait_group 0;" ::: "memory")

__device__ __forceinline__ uint32_t swz(int row, int seg) {
    return (uint32_t)(row * 256 + ((seg ^ (row & 7)) << 4));
}

__device__ __forceinline__ void cp_tile(uint32_t dst_base, int rowBase, int tid) {
    size_t gsrc = __cvta_generic_to_global(g_fbf) + (size_t)rowBase * 256;
    #pragma unroll
    for (int it = 0; it < 4; it++) {
        int u = it * NTHR + tid;         // 2048 16B units
        int row = u >> 4, seg = u & 15;
        CP_ASYNC16(dst_base + swz(row, seg), (const void*)(gsrc + (size_t)u * 16));
    }
}

// ---------------------------------------------------------------------------
// Kernel 1: normalize rows (clamp at 1e-8); fp32 + bf16*SQRT_C copies; zero state
// ---------------------------------------------------------------------------
__global__ void prep_kernel(const float* __restrict__ features) {
    int warp = threadIdx.x >> 5, lane = threadIdx.x & 31;
    int row = blockIdx.x * 8 + warp;

    float4 v = ((const float4*)(features + row * D))[lane];
    float ss = v.x * v.x + v.y * v.y + v.z * v.z + v.w * v.w;
    #pragma unroll
    for (int off = 16; off; off >>= 1) ss += __shfl_xor_sync(0xffffffffu, ss, off);
    float sc = 1.0f / fmaxf(sqrtf(ss), 1e-8f);

    float4 nv;
    nv.x = v.x * sc; nv.y = v.y * sc; nv.z = v.z * sc; nv.w = v.w * sc;
    ((float4*)(g_fn + (size_t)row * D))[lane] = nv;

    __nv_bfloat162 p0 = __floats2bfloat162_rn(nv.x * SQRT_C, nv.y * SQRT_C);
    __nv_bfloat162 p1 = __floats2bfloat162_rn(nv.z * SQRT_C, nv.w * SQRT_C);
    uint2 st;
    st.x = *(const uint32_t*)&p0;
    st.y = *(const uint32_t*)&p1;
    ((uint2*)(g_fbf + (size_t)row * D))[lane] = st;

    int gt = blockIdx.x * blockDim.x + threadIdx.x;
    if (gt < N) g_den[gt] = 0.0f;
    if (gt == 0) { g_loss = 0.0f; g_cnt_gemm = 0u; g_cnt_out = 0u; }
}

// ---------------------------------------------------------------------------
// Kernel 2: bucket sort of (label, idx). One CTA, 1024 threads, 96KB smem.
// ---------------------------------------------------------------------------
__global__ void sort_kernel(const float* __restrict__ labels) {
    extern __shared__ char smem[];
    unsigned long long* keys = (unsigned long long*)smem;       // 64 KB
    unsigned* cnt = (unsigned*)(smem + 65536);                  // 16 KB
    unsigned* bst = (unsigned*)(smem + 65536 + 16384);          // 16 KB
    __shared__ unsigned wtot[33];

    const int tid = threadIdx.x;
    const int wid = tid >> 5, lane = tid & 31;

    for (int b = tid; b < NBUCK; b += 1024) cnt[b] = 0u;
    __syncthreads();
    #pragma unroll
    for (int it = 0; it < 8; it++) {
        float lv = labels[it * 1024 + tid];
        int b = max(0, min(NBUCK - 1, (int)(lv * (float)NBUCK)));
        atomicAdd(&cnt[b], 1u);
    }
    __syncthreads();
    unsigned loc[4]; unsigned s = 0u;
    #pragma unroll
    for (int j = 0; j < 4; j++) { loc[j] = s; s += cnt[tid * 4 + j]; }
    unsigned incl = s;
    #pragma unroll
    for (int off = 1; off < 32; off <<= 1) {
        unsigned v = __shfl_up_sync(0xffffffffu, incl, off);
        if (lane >= off) incl += v;
    }
    if (lane == 31) wtot[wid + 1] = incl;
    if (tid == 0) wtot[0] = 0u;
    __syncthreads();
    if (tid == 0)
        for (int w = 1; w <= 32; w++) wtot[w] += wtot[w - 1];
    __syncthreads();
    unsigned base = wtot[wid] + incl - s;
    #pragma unroll
    for (int j = 0; j < 4; j++) bst[tid * 4 + j] = base + loc[j];
    __syncthreads();
    #pragma unroll
    for (int it = 0; it < 8; it++) {
        int k = it * 1024 + tid;
        float lv = labels[k];
        int b = max(0, min(NBUCK - 1, (int)(lv * (float)NBUCK)));
        unsigned pos = atomicAdd(&bst[b], 1u);
        keys[pos] = ((unsigned long long)__float_as_uint(lv) << 32) | (unsigned)k;
    }
    __syncthreads();
    #pragma unroll 1
    for (int b = tid; b < NBUCK; b += 1024) {
        unsigned st = (b == 0) ? 0u : bst[b - 1];
        unsigned n = cnt[b];
        for (unsigned x = st + 1; x < st + n; x++) {
            unsigned long long v = keys[x];
            unsigned y = x;
            while (y > st && keys[y - 1] > v) { keys[y] = keys[y - 1]; y--; }
            keys[y] = v;
        }
    }
    __syncthreads();
    for (int k = tid; k < N; k += 1024) {
        unsigned long long v = keys[k];
        g_slab[k] = __uint_as_float((unsigned)(v >> 32));
        g_sidx[k] = (int)(v & 0xffffffffu);
    }
}

// ---------------------------------------------------------------------------
// Kernel 3: permute features into sorted order (smem staging) + 16-row
// subchunk sums. 64 CTAs x 256 threads; CTA c = sorted rows [c*128, +128).
// ---------------------------------------------------------------------------
__global__ void perm_kernel() {
    extern __shared__ char smem[];
    float* sData = (float*)smem;                 // 64 KB: 128 rows x 128 f32
    int* sIdx = (int*)(smem + 65536);            // 512 B
    const int tid = threadIdx.x;
    const int c = blockIdx.x;

    if (tid < 128) sIdx[tid] = g_sidx[c * 128 + tid];
    __syncthreads();

    // gather 128 rows (independent addresses -> deep MLP)
    #pragma unroll
    for (int it = 0; it < 16; it++) {
        int u = it * 256 + tid;                  // 4096 float4 units
        int row = u >> 5, seg = u & 31;
        ((float4*)sData)[u] = ((const float4*)(g_fn + (size_t)sIdx[row] * D))[seg];
    }
    __syncthreads();

    // write coalesced
    float4* dst = (float4*)(g_fp + (size_t)c * 128 * D);
    #pragma unroll
    for (int it = 0; it < 16; it++) {
        int u = it * 256 + tid;
        dst[u] = ((const float4*)sData)[u];
    }
    // 16-row subchunk sums: 8 subchunks x 128 cols = 1024 values, 4 per thread
    #pragma unroll
    for (int t = 0; t < 4; t++) {
        int idx = t * 256 + tid;
        int sub = idx >> 7, col = idx & 127;
        float s = 0.0f;
        #pragma unroll
        for (int r = 0; r < 16; r++) s += sData[(sub * 16 + r) * D + col];
        g_ssum[(size_t)(c * 8 + sub) * D + col] = s;
    }
}

// ---------------------------------------------------------------------------
// Kernel 4a: exclusive scan of 512 subchunk sums per column. 1 CTA x 512.
// thread = (quarter q, column d); two-pass with quarter offsets in smem.
// ---------------------------------------------------------------------------
__global__ void scan_off_kernel() {
    __shared__ float qsum[4][128];
    const int d = threadIdx.x & 127;
    const int q = threadIdx.x >> 7;          // 0..3, 128 subchunks each

    float s = 0.0f;
    #pragma unroll 16
    for (int k = 0; k < 128; k++) s += g_ssum[(size_t)(q * 128 + k) * D + d];
    qsum[q][d] = s;
    __syncthreads();
    float off = 0.0f;
    #pragma unroll
    for (int j = 0; j < 4; j++) off += (j < q) ? qsum[j][d] : 0.0f;

    float run = off;
    #pragma unroll 16
    for (int k = 0; k < 128; k++) {
        size_t idx = (size_t)(q * 128 + k) * D + d;
        g_soff[idx] = run;
        run += g_ssum[idx];
    }
}

// ---------------------------------------------------------------------------
// Kernel 4b: write prefix rows. 512 CTAs x 128 threads; CTA s = subchunk s.
// ---------------------------------------------------------------------------
__global__ void scan2_kernel() {
    const int d = threadIdx.x;
    const int s = blockIdx.x;
    const float* src = g_fp + (size_t)s * 16 * D + d;
    float* dst = g_pref + (size_t)s * 16 * D + d;
    float run = g_soff[(size_t)s * D + d];
    #pragma unroll
    for (int r = 0; r < 16; r++) {
        dst[(size_t)r * D] = run;
        run += src[(size_t)r * D];
    }
    if (s == NSUB - 1) g_pref[(size_t)N * D + d] = run;
}

// ---------------------------------------------------------------------------
// Kernel 5: persistent fused HMMA GEMM over the upper triangle (denominator
// only), then grid barrier, then final loss (smem binary searches + prefix
// dots). 148 CTAs x 512 threads.
// ---------------------------------------------------------------------------
__global__ void __launch_bounds__(NTHR, 1)
main_kernel(float* __restrict__ out) {
    extern __shared__ char smem[];
    const uint32_t sb = smem_u32(smem);
    const int tid  = threadIdx.x;
    const int wid  = tid >> 5;
    const int lane = tid & 31;
    const int bid  = (int)blockIdx.x;
    const int wm = wid & 3;
    const int wn = wid >> 2;
    const int quad = lane >> 2;
    const int qt   = lane & 3;

    const int rowA = wm * 32 + (lane & 15);
    const int hiA  = lane >> 4;
    const int r7A  = rowA & 7;
    const uint32_t aRowOff = (uint32_t)(rowA * 256);
    const int g   = lane >> 3;
    const int r8  = lane & 7;
    const int nrowb = wn * 32 + ((g >> 1) << 3) + r8;
    const int segbLo = g & 1;
    const uint32_t bBase = sb + SM_RES + (uint32_t)(nrowb * 256);

    const int t0 = ((int)bid * NTT) / NCTA;
    const int t1 = (((int)bid + 1) * NTT) / NCTA;

    int tj = 0, rem = t0;
    while (rem >= tj + 1) { rem -= tj + 1; tj++; }
    int ti = rem;

    cp_tile(sb + SM_RES, tj * 128, tid);
    cp_tile(sb + SM_STR + (t0 & 1) * 32768, ti * 128, tid);
    CP_COMMIT();
    CP_WAIT0();
    __syncthreads();

    float cdn[8];
    #pragma unroll
    for (int p = 0; p < 8; p++) cdn[p] = 0.0f;

    for (int t = t0; t < t1; t++) {
        const int s = t & 1;
        const bool have_next = (t + 1) < t1;
        int nti = ti + 1, ntj = tj;
        if (nti > tj) { ntj = tj + 1; nti = 0; }
        const bool strip_change = have_next && (ntj != tj);

        if (have_next) {
            cp_tile(sb + SM_STR + ((t + 1) & 1) * 32768, nti * 128, tid);
            CP_COMMIT();
        }

        float acc[2][4][4];
        #pragma unroll
        for (int mi = 0; mi < 2; mi++)
            #pragma unroll
            for (int ni = 0; ni < 4; ni++)
                #pragma unroll
                for (int r = 0; r < 4; r++) acc[mi][ni][r] = 0.0f;

        const uint32_t aBase = sb + SM_STR + s * 32768 + aRowOff;
        #pragma unroll
        for (int k = 0; k < 8; k++) {
            uint32_t a[2][4];
            #pragma unroll
            for (int mi = 0; mi < 2; mi++) {
                uint32_t addr = aBase + mi * 4096 + ((((k * 2 + hiA) ^ r7A)) << 4);
                LDSM_X4(a[mi][0], a[mi][1], a[mi][2], a[mi][3], addr);
            }
            uint32_t b[4][2];
            #pragma unroll
            for (int p = 0; p < 2; p++) {
                uint32_t addr = bBase + p * 4096 + ((((k * 2 + segbLo) ^ r8)) << 4);
                LDSM_X4(b[2 * p][0], b[2 * p][1], b[2 * p + 1][0], b[2 * p + 1][1], addr);
            }
            #pragma unroll
            for (int mi = 0; mi < 2; mi++)
                #pragma unroll
                for (int ni = 0; ni < 4; ni++)
                    MMA16816(acc[mi][ni], a[mi], b[ni]);
        }

        float dn[4] = {0.0f, 0.0f, 0.0f, 0.0f};
        if (ti == tj) {
            #pragma unroll
            for (int mi = 0; mi < 2; mi++)
                #pragma unroll
                for (int rh = 0; rh < 2; rh++) {
                    const int slot = mi * 2 + rh;
                    const int selfnl = wm * 32 + mi * 16 + quad + rh * 8;
                    #pragma unroll
                    for (int p = 0; p < 8; p++) {
                        const int ni = p >> 1, c = p & 1;
                        const int nl = wn * 32 + ni * 8 + qt * 2 + c;
                        float e = ex2(acc[mi][ni][rh * 2 + c]);
                        dn[slot] += (nl == selfnl) ? 0.0f : e;
                    }
                }
        } else {
            #pragma unroll
            for (int p = 0; p < 8; p++) {
                const int ni = p >> 1, c = p & 1;
                float a0 = 0.0f;
                #pragma unroll
                for (int mi = 0; mi < 2; mi++)
                    #pragma unroll
                    for (int rh = 0; rh < 2; rh++) {
                        float e = ex2(acc[mi][ni][rh * 2 + c]);
                        dn[mi * 2 + rh] += e;
                        a0 += e;
                    }
                cdn[p] += a0;
            }
        }

        #pragma unroll
        for (int s2 = 0; s2 < 4; s2++) {
            float a = dn[s2];
            a += __shfl_xor_sync(0xffffffffu, a, 1);
            a += __shfl_xor_sync(0xffffffffu, a, 2);
            if (qt == 0) {
                int gim = ti * 128 + wm * 32 + (s2 >> 1) * 16 + quad + (s2 & 1) * 8;
                atomicAdd(&g_den[gim], a);
            }
        }

        if (strip_change || !have_next) {
            #pragma unroll
            for (int p = 0; p < 8; p++) {
                float a = cdn[p];
                #pragma unroll
                for (int off = 4; off <= 16; off <<= 1)
                    a += __shfl_xor_sync(0xffffffffu, a, off);
                if (quad == 0) {
                    int gj = tj * 128 + wn * 32 + (p >> 1) * 8 + qt * 2 + (p & 1);
                    atomicAdd(&g_den[gj], a);
                }
                cdn[p] = 0.0f;
            }
        }

        CP_WAIT0();
        __syncthreads();
        if (strip_change) {
            cp_tile(sb + SM_RES, ntj * 128, tid);
            CP_COMMIT();
            CP_WAIT0();
            __syncthreads();
        }
        ti = nti; tj = ntj;
    }

    // ===================== grid barrier =====================
    __threadfence();
    __syncthreads();
    if (tid == 0) {
        atomicAdd(&g_cnt_gemm, 1u);
        while (ld_acq(&g_cnt_gemm) < (unsigned)NCTA) __nanosleep(128);
    }
    __syncthreads();

    // ===================== final loss =====================
    {
        float* sslab = (float*)smem;          // 32 KB (GEMM buffers dead now)
        for (int k = tid; k < N; k += NTHR) sslab[k] = g_slab[k];
        __syncthreads();

        float wsum = 0.0f;
        #pragma unroll 1
        for (int k = bid * 16 + wid; k < N; k += NCTA * 16) {
            float li = sslab[k];
            int l = 0, r = N;
            while (l < r) { int m = (l + r) >> 1; if (li - sslab[m] < THRESH) r = m; else l = m + 1; }
            const int lo = l;
            l = 0; r = N;
            while (l < r) { int m = (l + r) >> 1; if (sslab[m] - li < THRESH) l = m + 1; else r = m; }
            const int hi = l;

            float dot = 0.0f;
            const float* fk = g_fp + (size_t)k * D;
            const float* Ph = g_pref + (size_t)hi * D;
            const float* Pl = g_pref + (size_t)lo * D;
            #pragma unroll
            for (int qd = 0; qd < 4; qd++) {
                int d = lane + qd * 32;
                dot += fk[d] * (Ph[d] - Pl[d]);
            }
            #pragma unroll
            for (int off = 16; off; off >>= 1)
                dot += __shfl_xor_sync(0xffffffffu, dot, off);

            if (lane == 0) {
                int i = g_sidx[k];
                float pcv = (float)(hi - lo - 1);
                wsum += (dot - 1.0f) * INV_T / pcv - LN2 * log2f(g_den[i]);
            }
        }
        if (lane == 0) atomicAdd(&g_loss, wsum);

        __threadfence();
        __syncthreads();
        if (tid == 0) {
            unsigned tk = atomicAdd(&g_cnt_out, 1u);
            if (tk == (unsigned)(NCTA - 1))
                out[0] = -(atomicAdd(&g_loss, 0.0f)) / (float)N;
        }
    }
}

// ---------------------------------------------------------------------------
extern "C" void kernel_launch(void* const* d_in, const int* in_sizes, int n_in,
                              void* d_out, int out_size) {
    const float* features = (const float*)d_in[0];
    const float* labels   = (const float*)d_in[1];
    float* out = (float*)d_out;

    cudaFuncSetAttribute(main_kernel, cudaFuncAttributeMaxDynamicSharedMemorySize, SM_TOTAL);
    cudaFuncSetAttribute(sort_kernel, cudaFuncAttributeMaxDynamicSharedMemorySize, 98304);
    cudaFuncSetAttribute(perm_kernel, cudaFuncAttributeMaxDynamicSharedMemorySize, 66048);

    prep_kernel<<<N / 8, 256>>>(features);
    sort_kernel<<<1, 1024, 98304>>>(labels);
    perm_kernel<<<64, 256, 66048>>>();
    scan_off_kernel<<<1, 512>>>();
    scan2_kernel<<<NSUB, 128>>>();
    main_kernel<<<NCTA, NTHR, SM_TOTAL>>>(out);
}

// round 12
// speedup vs baseline: 1.4518x; 1.4518x over previous
#include <cuda_runtime.h>
#include <cuda_bf16.h>
#include <cstdint>
#include <math.h>

#define N 8192
#define D 128
#define NCTA 148
#define NTT 2080               /* upper-triangle tiles: 64*65/2 */
#define NTHR 512
#define NBUCK 4096
#define LN2 0.69314718055994531f
#define SQRT_C 4.5398160486f   /* sqrt((1/0.07)*log2(e)) */
#define THRESH 0.1f

// Scratch (no cudaMalloc allowed)
__device__ __nv_bfloat16 g_fraw[N * D];      // normalized * SQRT_C, bf16, original order
__device__ __nv_bfloat16 g_fbf[N * D];       // same, label-sorted order
__device__ float g_slab[N];                  // sorted labels
__device__ int   g_sidx[N];                  // sorted -> original index
__device__ float g_den[N];                   // per sorted row
__device__ float g_ps[N];                    // in log2 units
__device__ float g_pc[N];
__device__ float g_loss;
__device__ unsigned g_cnt_gemm, g_cnt_out;

// ---- main kernel SMEM layout (bytes) ----
#define SM_RES   0          /* resident j-strip tile, 32 KB, XOR-swizzled */
#define SM_STR   32768      /* 2 x 32 KB double-buffered streaming A tiles */
#define SM_LABI  98304      /* 2 x 512B double-buffered row labels */
#define SM_LABJ  99328      /* 512B column labels (per strip) */
#define SM_TOTAL 99840

__device__ __forceinline__ uint32_t smem_u32(const void* p) {
    uint32_t a;
    asm("{ .reg .u64 t; cvta.to.shared.u64 t, %1; cvt.u32.u64 %0, t; }" : "=r"(a) : "l"(p));
    return a;
}
__device__ __forceinline__ float ex2(float x) {
    float r;
    asm("ex2.approx.ftz.f32 %0, %1;" : "=f"(r) : "f"(x));
    return r;
}
__device__ __forceinline__ unsigned ld_acq(unsigned* p) {
    unsigned v;
    asm volatile("ld.acquire.gpu.u32 %0, [%1];" : "=r"(v) : "l"(p) : "memory");
    return v;
}

#define LDSM_X4(r0, r1, r2, r3, addr) \
    asm volatile("ldmatrix.sync.aligned.m8n8.x4.shared.b16 {%0,%1,%2,%3}, [%4];" \
                 : "=r"(r0), "=r"(r1), "=r"(r2), "=r"(r3) : "r"(addr))

#define MMA16816(d, a, b) \
    asm volatile("mma.sync.aligned.m16n8k16.row.col.f32.bf16.bf16.f32 " \
                 "{%0,%1,%2,%3}, {%4,%5,%6,%7}, {%8,%9}, {%0,%1,%2,%3};" \
                 : "+f"((d)[0]), "+f"((d)[1]), "+f"((d)[2]), "+f"((d)[3]) \
                 : "r"((a)[0]), "r"((a)[1]), "r"((a)[2]), "r"((a)[3]), \
                   "r"((b)[0]), "r"((b)[1]))

#define CP_ASYNC16(dst, src) \
    asm volatile("cp.async.cg.shared.global [%0], [%1], 16;" \
                 :: "r"(dst), "l"(src) : "memory")
#define CP_COMMIT() asm volatile("cp.async.commit_group;" ::: "memory")
#define CP_WAIT0()  asm volatile("cp.async.wait_group 0;" ::: "memory")

__device__ __forceinline__ uint32_t swz(int row, int seg) {
    return (uint32_t)(row * 256 + ((seg ^ (row & 7)) << 4));
}

// cp.async a 128-row tile of the SORTED bf16 matrix into swizzled smem
__device__ __forceinline__ void cp_tile(uint32_t dst_base, int rowBase, int tid) {
    size_t gsrc = __cvta_generic_to_global(g_fbf) + (size_t)rowBase * 256;
    #pragma unroll
    for (int it = 0; it < 4; it++) {
        int u = it * NTHR + tid;         // 2048 16B units
        int row = u >> 4, seg = u & 15;
        CP_ASYNC16(dst_base + swz(row, seg), (const void*)(gsrc + (size_t)u * 16));
    }
}

// ---------------------------------------------------------------------------
// Kernel 1: normalize rows (clamp at 1e-8), write bf16*SQRT_C, zero state
// ---------------------------------------------------------------------------
__global__ void prep_kernel(const float* __restrict__ features) {
    int warp = threadIdx.x >> 5, lane = threadIdx.x & 31;
    int row = blockIdx.x * 8 + warp;

    float4 v = ((const float4*)(features + row * D))[lane];
    float ss = v.x * v.x + v.y * v.y + v.z * v.z + v.w * v.w;
    #pragma unroll
    for (int off = 16; off; off >>= 1) ss += __shfl_xor_sync(0xffffffffu, ss, off);
    float sc = SQRT_C / fmaxf(sqrtf(ss), 1e-8f);

    __nv_bfloat162 p0 = __floats2bfloat162_rn(v.x * sc, v.y * sc);
    __nv_bfloat162 p1 = __floats2bfloat162_rn(v.z * sc, v.w * sc);
    uint2 st;
    st.x = *(const uint32_t*)&p0;
    st.y = *(const uint32_t*)&p1;
    ((uint2*)(g_fraw + (size_t)row * D))[lane] = st;

    int gt = blockIdx.x * blockDim.x + threadIdx.x;
    if (gt < N) { g_den[gt] = 0.0f; g_ps[gt] = 0.0f; g_pc[gt] = 0.0f; }
    if (gt == 0) { g_loss = 0.0f; g_cnt_gemm = 0u; g_cnt_out = 0u; }
}

// ---------------------------------------------------------------------------
// Kernel 2: bucket sort of (label, idx). One CTA, 1024 threads, 96KB smem.
// ---------------------------------------------------------------------------
__global__ void sort_kernel(const float* __restrict__ labels) {
    extern __shared__ char smem[];
    unsigned long long* keys = (unsigned long long*)smem;       // 64 KB
    unsigned* cnt = (unsigned*)(smem + 65536);                  // 16 KB
    unsigned* bst = (unsigned*)(smem + 65536 + 16384);          // 16 KB
    __shared__ unsigned wtot[33];

    const int tid = threadIdx.x;
    const int wid = tid >> 5, lane = tid & 31;

    for (int b = tid; b < NBUCK; b += 1024) cnt[b] = 0u;
    __syncthreads();
    #pragma unroll
    for (int it = 0; it < 8; it++) {
        float lv = labels[it * 1024 + tid];
        int b = max(0, min(NBUCK - 1, (int)(lv * (float)NBUCK)));
        atomicAdd(&cnt[b], 1u);
    }
    __syncthreads();
    unsigned loc[4]; unsigned s = 0u;
    #pragma unroll
    for (int j = 0; j < 4; j++) { loc[j] = s; s += cnt[tid * 4 + j]; }
    unsigned incl = s;
    #pragma unroll
    for (int off = 1; off < 32; off <<= 1) {
        unsigned v = __shfl_up_sync(0xffffffffu, incl, off);
        if (lane >= off) incl += v;
    }
    if (lane == 31) wtot[wid + 1] = incl;
    if (tid == 0) wtot[0] = 0u;
    __syncthreads();
    if (tid == 0)
        for (int w = 1; w <= 32; w++) wtot[w] += wtot[w - 1];
    __syncthreads();
    unsigned base = wtot[wid] + incl - s;
    #pragma unroll
    for (int j = 0; j < 4; j++) bst[tid * 4 + j] = base + loc[j];
    __syncthreads();
    #pragma unroll
    for (int it = 0; it < 8; it++) {
        int k = it * 1024 + tid;
        float lv = labels[k];
        int b = max(0, min(NBUCK - 1, (int)(lv * (float)NBUCK)));
        unsigned pos = atomicAdd(&bst[b], 1u);
        keys[pos] = ((unsigned long long)__float_as_uint(lv) << 32) | (unsigned)k;
    }
    __syncthreads();
    #pragma unroll 1
    for (int b = tid; b < NBUCK; b += 1024) {
        unsigned st = (b == 0) ? 0u : bst[b - 1];
        unsigned n = cnt[b];
        for (unsigned x = st + 1; x < st + n; x++) {
            unsigned long long v = keys[x];
            unsigned y = x;
            while (y > st && keys[y - 1] > v) { keys[y] = keys[y - 1]; y--; }
            keys[y] = v;
        }
    }
    __syncthreads();
    for (int k = tid; k < N; k += 1024) {
        unsigned long long v = keys[k];
        g_slab[k] = __uint_as_float((unsigned)(v >> 32));
        g_sidx[k] = (int)(v & 0xffffffffu);
    }
}

// ---------------------------------------------------------------------------
// Kernel 3: permute bf16 feature rows into label-sorted order. 64 CTAs x 256.
// ---------------------------------------------------------------------------
__global__ void perm_kernel() {
    __shared__ int sIdx[128];
    const int tid = threadIdx.x;
    const int c = blockIdx.x;

    if (tid < 128) sIdx[tid] = g_sidx[c * 128 + tid];
    __syncthreads();

    const uint4* src = (const uint4*)g_fraw;           // 16 uint4 per 256B row
    uint4* dst = (uint4*)(g_fbf + (size_t)c * 128 * D);
    #pragma unroll
    for (int it = 0; it < 8; it++) {
        int u = it * 256 + tid;                         // 2048 units
        int row = u >> 4, seg = u & 15;
        dst[u] = src[(size_t)sIdx[row] * 16 + seg];
    }
}

// ---------------------------------------------------------------------------
// Kernel 4: persistent fused HMMA GEMM over the upper triangle in SORTED
// order, column-major strip walk. Band tiles (label ranges overlap) get the
// dual row/col ps/pc epilogue; the rest get denominator-only. Finalize after
// a counter grid-barrier.
// ---------------------------------------------------------------------------
__global__ void __launch_bounds__(NTHR, 1)
main_kernel(float* __restrict__ out) {
    extern __shared__ char smem[];
    const uint32_t sb = smem_u32(smem);
    const int tid  = threadIdx.x;
    const int wid  = tid >> 5;
    const int lane = tid & 31;
    const int bid  = (int)blockIdx.x;
    const int wm = wid & 3;          // 0..3 -> m-block of 32
    const int wn = wid >> 2;         // 0..3 -> n-block of 32
    const int quad = lane >> 2;
    const int qt   = lane & 3;

    // --- ldmatrix per-lane bases ---
    const int rowA = wm * 32 + (lane & 15);
    const int hiA  = lane >> 4;
    const int r7A  = rowA & 7;
    const uint32_t aRowOff = (uint32_t)(rowA * 256);
    const int g   = lane >> 3;
    const int r8  = lane & 7;
    const int nrowb = wn * 32 + ((g >> 1) << 3) + r8;
    const int segbLo = g & 1;
    const uint32_t bBase = sb + SM_RES + (uint32_t)(nrowb * 256);

    const int t0 = ((int)bid * NTT) / NCTA;
    const int t1 = (((int)bid + 1) * NTT) / NCTA;

    // map t0 -> (tj, ti): column-major triangle, strip tj has tj+1 tiles
    int tj = 0, rem = t0;
    while (rem >= tj + 1) { rem -= tj + 1; tj++; }
    int ti = rem;

    size_t slab_g = __cvta_generic_to_global(g_slab);

    // prologue: resident B(tj) + column labels + first A(ti) + row labels
    cp_tile(sb + SM_RES, tj * 128, tid);
    cp_tile(sb + SM_STR + (t0 & 1) * 32768, ti * 128, tid);
    if (tid < 32) CP_ASYNC16(sb + SM_LABJ + tid * 16, (const void*)(slab_g + (size_t)tj * 512 + tid * 16));
    else if (tid < 64)
        CP_ASYNC16(sb + SM_LABI + (t0 & 1) * 512 + (tid - 32) * 16,
                   (const void*)(slab_g + (size_t)ti * 512 + (tid - 32) * 16));
    CP_COMMIT();
    CP_WAIT0();
    __syncthreads();

    // column labels for my 8 (ni,c) pairs
    float lj[8];
    #pragma unroll
    for (int p = 0; p < 8; p++)
        lj[p] = ((const float*)(smem + SM_LABJ))[wn * 32 + (p >> 1) * 8 + qt * 2 + (p & 1)];

    // column partials (registers across the strip)
    float cdn[8], cps[8], cpc[8];
    #pragma unroll
    for (int p = 0; p < 8; p++) { cdn[p] = 0.0f; cps[p] = 0.0f; cpc[p] = 0.0f; }

    for (int t = t0; t < t1; t++) {
        const int s = t & 1;
        const bool have_next = (t + 1) < t1;
        int nti = ti + 1, ntj = tj;
        if (nti > tj) { ntj = tj + 1; nti = 0; }
        const bool strip_change = have_next && (ntj != tj);

        // prefetch A(t+1) + row labels(t+1)
        if (have_next) {
            cp_tile(sb + SM_STR + ((t + 1) & 1) * 32768, nti * 128, tid);
            if (tid < 32)
                CP_ASYNC16(sb + SM_LABI + ((t + 1) & 1) * 512 + tid * 16,
                           (const void*)(slab_g + (size_t)nti * 512 + tid * 16));
            CP_COMMIT();
        }

        // ---- mainloop: 128x128 tile, K=128 ----
        float acc[2][4][4];
        #pragma unroll
        for (int mi = 0; mi < 2; mi++)
            #pragma unroll
            for (int ni = 0; ni < 4; ni++)
                #pragma unroll
                for (int r = 0; r < 4; r++) acc[mi][ni][r] = 0.0f;

        const uint32_t aBase = sb + SM_STR + s * 32768 + aRowOff;
        #pragma unroll
        for (int k = 0; k < 8; k++) {
            uint32_t a[2][4];
            #pragma unroll
            for (int mi = 0; mi < 2; mi++) {
                uint32_t addr = aBase + mi * 4096 + ((((k * 2 + hiA) ^ r7A)) << 4);
                LDSM_X4(a[mi][0], a[mi][1], a[mi][2], a[mi][3], addr);
            }
            uint32_t b[4][2];
            #pragma unroll
            for (int p = 0; p < 2; p++) {
                uint32_t addr = bBase + p * 4096 + ((((k * 2 + segbLo) ^ r8)) << 4);
                LDSM_X4(b[2 * p][0], b[2 * p][1], b[2 * p + 1][0], b[2 * p + 1][1], addr);
            }
            #pragma unroll
            for (int mi = 0; mi < 2; mi++)
                #pragma unroll
                for (int ni = 0; ni < 4; ni++)
                    MMA16816(acc[mi][ni], a[mi], b[ni]);
        }

        // labels + band test for this tile
        const float* slabI = (const float*)(smem + SM_LABI + s * 512);
        const bool band = (ti == tj) ||
            (((const float*)(smem + SM_LABJ))[0] - slabI[127] < THRESH);

        float li[4];
        #pragma unroll
        for (int s2 = 0; s2 < 4; s2++)
            li[s2] = slabI[wm * 32 + (s2 >> 1) * 16 + quad + (s2 & 1) * 8];

        // ---- fused epilogue (acc is already the ex2 argument, log2 units) ----
        float dn[4] = {0, 0, 0, 0}, ps[4] = {0, 0, 0, 0}, pc[4] = {0, 0, 0, 0};
        if (ti == tj) {
            // diagonal: row stats only, self-excluded
            #pragma unroll
            for (int mi = 0; mi < 2; mi++) {
                #pragma unroll
                for (int rh = 0; rh < 2; rh++) {
                    const int slot = mi * 2 + rh;
                    const int selfnl = wm * 32 + mi * 16 + quad + rh * 8;
                    const float lm = li[slot];
                    #pragma unroll
                    for (int p = 0; p < 8; p++) {
                        const int ni = p >> 1, c = p & 1;
                        float u = acc[mi][ni][rh * 2 + c];
                        const int nl = wn * 32 + ni * 8 + qt * 2 + c;
                        bool self = (nl == selfnl);
                        float e = ex2(u);
                        dn[slot] += self ? 0.0f : e;
                        bool pos = (fabsf(lm - lj[p]) < THRESH) && !self;
                        ps[slot] += pos ? u : 0.0f;
                        pc[slot] += pos ? 1.0f : 0.0f;
                    }
                }
            }
        } else if (band) {
            // off-diagonal band: dual row + column stats
            #pragma unroll
            for (int p = 0; p < 8; p++) {
                const int ni = p >> 1, c = p & 1;
                const float ljp = lj[p];
                float a0 = 0.0f, a1 = 0.0f, a2 = 0.0f;
                #pragma unroll
                for (int mi = 0; mi < 2; mi++) {
                    #pragma unroll
                    for (int rh = 0; rh < 2; rh++) {
                        const int slot = mi * 2 + rh;
                        float u = acc[mi][ni][rh * 2 + c];
                        float e = ex2(u);
                        dn[slot] += e;
                        a0 += e;
                        bool pos = fabsf(li[slot] - ljp) < THRESH;
                        float up = pos ? u : 0.0f;
                        float op = pos ? 1.0f : 0.0f;
                        ps[slot] += up;  a1 += up;
                        pc[slot] += op;  a2 += op;
                    }
                }
                cdn[p] += a0; cps[p] += a1; cpc[p] += a2;
            }
        } else {
            // far off-diagonal: denominator only
            #pragma unroll
            for (int p = 0; p < 8; p++) {
                const int ni = p >> 1, c = p & 1;
                float a0 = 0.0f;
                #pragma unroll
                for (int mi = 0; mi < 2; mi++) {
                    #pragma unroll
                    for (int rh = 0; rh < 2; rh++) {
                        float e = ex2(acc[mi][ni][rh * 2 + c]);
                        dn[mi * 2 + rh] += e;
                        a0 += e;
                    }
                }
                cdn[p] += a0;
            }
        }

        // ---- row flush: every tile (2-round qt shuffle) ----
        #pragma unroll
        for (int s2 = 0; s2 < 4; s2++) {
            float a = dn[s2];
            a += __shfl_xor_sync(0xffffffffu, a, 1);
            a += __shfl_xor_sync(0xffffffffu, a, 2);
            int gim = ti * 128 + wm * 32 + (s2 >> 1) * 16 + quad + (s2 & 1) * 8;
            if (band) {
                float b2 = ps[s2], c2 = pc[s2];
                b2 += __shfl_xor_sync(0xffffffffu, b2, 1);
                b2 += __shfl_xor_sync(0xffffffffu, b2, 2);
                c2 += __shfl_xor_sync(0xffffffffu, c2, 1);
                c2 += __shfl_xor_sync(0xffffffffu, c2, 2);
                if (qt == 0) {
                    atomicAdd(&g_den[gim], a);
                    atomicAdd(&g_ps[gim],  b2);
                    atomicAdd(&g_pc[gim],  c2);
                }
            } else if (qt == 0) {
                atomicAdd(&g_den[gim], a);
            }
        }

        // ---- column flush at strip end / range end ----
        if (strip_change || !have_next) {
            #pragma unroll
            for (int p = 0; p < 8; p++) {
                float a = cdn[p], b2 = cps[p], c2 = cpc[p];
                #pragma unroll
                for (int off = 4; off <= 16; off <<= 1) {
                    a  += __shfl_xor_sync(0xffffffffu, a, off);
                    b2 += __shfl_xor_sync(0xffffffffu, b2, off);
                    c2 += __shfl_xor_sync(0xffffffffu, c2, off);
                }
                if (quad == 0) {
                    int gj = tj * 128 + wn * 32 + (p >> 1) * 8 + qt * 2 + (p & 1);
                    atomicAdd(&g_den[gj], a);
                    atomicAdd(&g_ps[gj],  b2);
                    atomicAdd(&g_pc[gj],  c2);
                }
                cdn[p] = 0.0f; cps[p] = 0.0f; cpc[p] = 0.0f;
            }
        }

        CP_WAIT0();
        __syncthreads();
        if (strip_change) {
            cp_tile(sb + SM_RES, ntj * 128, tid);
            if (tid < 32)
                CP_ASYNC16(sb + SM_LABJ + tid * 16,
                           (const void*)(slab_g + (size_t)ntj * 512 + tid * 16));
            CP_COMMIT();
            CP_WAIT0();
            __syncthreads();
            #pragma unroll
            for (int p = 0; p < 8; p++)
                lj[p] = ((const float*)(smem + SM_LABJ))[wn * 32 + (p >> 1) * 8 + qt * 2 + (p & 1)];
        }
        ti = nti; tj = ntj;
    }

    // ===================== grid barrier =====================
    __threadfence();
    __syncthreads();
    if (tid == 0) {
        atomicAdd(&g_cnt_gemm, 1u);
        while (ld_acq(&g_cnt_gemm) < (unsigned)NCTA) __nanosleep(128);
    }
    __syncthreads();

    // ===================== finalize =====================
    {
        int r = bid * NTHR + tid;           // one row per thread; bid<16 active
        float term = 0.0f;
        if (r < N)
            term = g_ps[r] / g_pc[r] - log2f(g_den[r]);
        #pragma unroll
        for (int off = 16; off; off >>= 1)
            term += __shfl_xor_sync(0xffffffffu, term, off);
        if (lane == 0 && (bid * NTHR + wid * 32) < N)
            atomicAdd(&g_loss, term);

        __threadfence();
        __syncthreads();
        if (tid == 0) {
            unsigned tk = atomicAdd(&g_cnt_out, 1u);
            if (tk == (unsigned)(NCTA - 1))
                out[0] = -(LN2 * atomicAdd(&g_loss, 0.0f)) / (float)N;
        }
    }
}

// ---------------------------------------------------------------------------
extern "C" void kernel_launch(void* const* d_in, const int* in_sizes, int n_in,
                              void* d_out, int out_size) {
    const float* features = (const float*)d_in[0];
    const float* labels   = (const float*)d_in[1];
    float* out = (float*)d_out;

    cudaFuncSetAttribute(main_kernel, cudaFuncAttributeMaxDynamicSharedMemorySize, SM_TOTAL);
    cudaFuncSetAttribute(sort_kernel, cudaFuncAttributeMaxDynamicSharedMemorySize, 98304);

    prep_kernel<<<N / 8, 256>>>(features);
    sort_kernel<<<1, 1024, 98304>>>(labels);
    perm_kernel<<<64, 256>>>();
    main_kernel<<<NCTA, NTHR, SM_TOTAL>>>(out);
}